// round 3
// baseline (speedup 1.0000x reference)
#include <cuda_runtime.h>
#include <cstdint>
#include <cstddef>

#define T_N   1024
#define B_N   64
#define V_N   32000
#define H_N   512
#define GRID_R 128          // persistent CTAs (<=148 SMs, 1/SM)
#define COLS_PER 4          // H_N / GRID_R
#define NTHR  256
#define NBAR  (T_N + 2)

// ---------------- persistent device scratch (no allocations allowed) ----------------
__device__ float    g_embW0[(size_t)V_N * H_N];   // emb @ Wih0^T + bih0 + bhh0
__device__ float    g_h0[2][B_N * H_N];
__device__ float    g_h1[2][B_N * H_N];
__device__ unsigned g_bar[NBAR];

// ---------------- reset: deterministic state per launch / graph replay ----------------
__global__ void reset_kernel() {
    int i = blockIdx.x * blockDim.x + threadIdx.x;
    if (i < B_N * H_N) {
        g_h0[0][i] = 0.f; g_h0[1][i] = 0.f;
        g_h1[0][i] = 0.f; g_h1[1][i] = 0.f;
    }
    if (i < NBAR) g_bar[i] = 0u;
}

// ---------------- embW0[v][h] = sum_e emb[v][e]*Wih0[h][e] + bih0[h] + bhh0[h] ----------------
// 128x128 tile, K-chunks of 8, 256 threads, 8x8 microtile. V=32000=250*128, H=512=4*128.
__global__ __launch_bounds__(256) void embw_kernel(const float* __restrict__ A,
                                                   const float* __restrict__ W,
                                                   const float* __restrict__ bih,
                                                   const float* __restrict__ bhh) {
    __shared__ float As[8][132];
    __shared__ float Ws[8][132];
    const int tid   = threadIdx.x;
    const int hBase = blockIdx.x * 128;
    const int vBase = blockIdx.y * 128;
    const int lRow  = tid >> 1;
    const int lCol  = (tid & 1) * 4;
    const int tx    = tid & 15;
    const int ty    = tid >> 4;

    const float4* Ap = (const float4*)(A + (size_t)(vBase + lRow) * H_N + lCol);
    const float4* Wp = (const float4*)(W + (size_t)(hBase + lRow) * H_N + lCol);

    float acc[8][8];
#pragma unroll
    for (int i = 0; i < 8; i++)
#pragma unroll
        for (int j = 0; j < 8; j++) acc[i][j] = 0.f;

    float4 av = Ap[0];
    float4 wv = Wp[0];

    for (int k0 = 0; k0 < 512; k0 += 8) {
        __syncthreads();
        As[lCol + 0][lRow] = av.x; As[lCol + 1][lRow] = av.y;
        As[lCol + 2][lRow] = av.z; As[lCol + 3][lRow] = av.w;
        Ws[lCol + 0][lRow] = wv.x; Ws[lCol + 1][lRow] = wv.y;
        Ws[lCol + 2][lRow] = wv.z; Ws[lCol + 3][lRow] = wv.w;
        __syncthreads();
        if (k0 + 8 < 512) {
            av = Ap[(k0 + 8) >> 2];
            wv = Wp[(k0 + 8) >> 2];
        }
#pragma unroll
        for (int k = 0; k < 8; k++) {
            float a[8], w[8];
            *(float4*)&a[0] = *(const float4*)&As[k][ty * 8];
            *(float4*)&a[4] = *(const float4*)&As[k][ty * 8 + 4];
            *(float4*)&w[0] = *(const float4*)&Ws[k][tx * 8];
            *(float4*)&w[4] = *(const float4*)&Ws[k][tx * 8 + 4];
#pragma unroll
            for (int i = 0; i < 8; i++)
#pragma unroll
                for (int j = 0; j < 8; j++) acc[i][j] += a[i] * w[j];
        }
    }

#pragma unroll
    for (int i = 0; i < 8; i++) {
        const int v = vBase + ty * 8 + i;
        float* orow = &g_embW0[(size_t)v * H_N + hBase + tx * 8];
        float o[8];
#pragma unroll
        for (int j = 0; j < 8; j++) {
            int h = hBase + tx * 8 + j;
            o[j] = acc[i][j] + __ldg(&bih[h]) + __ldg(&bhh[h]);
        }
        *(float4*)&orow[0] = *(float4*)&o[0];
        *(float4*)&orow[4] = *(float4*)&o[4];
    }
}

// ---------------- persistent recurrence kernel ----------------
// SMEM (floats):  Hs[32768] | W0s[2048] | W1A[2048] | W1B[2048] | Rs[8448] | b1s[4]
#define OFF_HS   0
#define OFF_W0   32768
#define OFF_W1A  (OFF_W0 + 2048)
#define OFF_W1B  (OFF_W1A + 2048)
#define OFF_RS   (OFF_W1B + 2048)          // 8*32 rows, stride 33 (conflict-free)
#define OFF_B1   (OFF_RS + 8 * 32 * 33)
#define SMEM_FLOATS (OFF_B1 + 4)
#define SMEM_BYTES  (SMEM_FLOATS * 4)

__global__ __launch_bounds__(NTHR, 1) void rnn_kernel(const int*   __restrict__ input,
                                                      const float* __restrict__ Whh0,
                                                      const float* __restrict__ Wih1,
                                                      const float* __restrict__ Whh1,
                                                      const float* __restrict__ bih1,
                                                      const float* __restrict__ bhh1,
                                                      float*       __restrict__ out) {
    extern __shared__ float smem[];
    float* Hs  = smem + OFF_HS;
    float* W0s = smem + OFF_W0;
    float* W1A = smem + OFF_W1A;
    float* W1B = smem + OFF_W1B;
    float* Rs  = smem + OFF_RS;
    float* b1s = smem + OFF_B1;

    const int tid  = threadIdx.x;
    const int cid  = blockIdx.x;
    const int w    = tid >> 5;
    const int lane = tid & 31;
    const int cbase = cid * COLS_PER;

    // ---- preload this CTA's weight slices (rows cbase..cbase+3, contiguous) ----
    {
        const float4* s0 = (const float4*)(Whh0 + (size_t)cbase * H_N);
        const float4* s1 = (const float4*)(Wih1 + (size_t)cbase * H_N);
        const float4* s2 = (const float4*)(Whh1 + (size_t)cbase * H_N);
        for (int r = tid; r < 512; r += NTHR) {
            ((float4*)W0s)[r] = __ldg(&s0[r]);
            ((float4*)W1A)[r] = __ldg(&s1[r]);
            ((float4*)W1B)[r] = __ldg(&s2[r]);
        }
        if (tid < COLS_PER) b1s[tid] = __ldg(&bih1[cbase + tid]) + __ldg(&bhh1[cbase + tid]);
    }
    __syncthreads();

    // reduce-phase output mapping: thread -> one (b, c) output
    const int oi    = lane;
    const int b_r   = w * 8 + (oi >> 2);
    const int c_loc = oi & 3;
    const int c_r   = cbase + c_loc;

    const float4* W04 = (const float4*)W0s;
    const float4* WA4 = (const float4*)W1A;
    const float4* WB4 = (const float4*)W1B;
    const float4* Hs4 = (const float4*)Hs;

    for (int s = 1; s <= T_N + 1; s++) {
        const bool doH0 = (s <= T_N);
        const bool doH1 = (s >= 2);

        // ---- prefetch gathered input-projection value for h0 epilogue ----
        float xw = 0.f;
        if (doH0) {
            int tok = __ldg(&input[(s - 1) * B_N + b_r]);
            xw = __ldcg(&g_embW0[(size_t)tok * H_N + c_r]);
        }

        // ---- stage h0[s-2] -> SMEM (async; overlapped with h1B below) ----
        {
            const float* src = g_h0[s & 1];
            unsigned sdst = (unsigned)__cvta_generic_to_shared(Hs);
#pragma unroll
            for (int r = 0; r < 32; r++) {
                int idx = tid + NTHR * r;          // float4 index
                asm volatile("cp.async.cg.shared.global [%0], [%1], 16;\n"
                             :: "r"(sdst + idx * 16), "l"(src + idx * 4));
            }
            asm volatile("cp.async.commit_group;\n");
        }

        // ---- h1B: h1[s-3] @ Whh1^T, straight from L2 (no SMEM stage) ----
        float h1b = 0.f;
        if (doH1) {
            float accB[8][4];
#pragma unroll
            for (int i = 0; i < 8; i++)
#pragma unroll
                for (int c = 0; c < 4; c++) accB[i][c] = 0.f;
            const float4* h1p = (const float4*)g_h1[(s + 1) & 1];
#pragma unroll
            for (int j = 0; j < 4; j++) {
                float4 wb[4];
#pragma unroll
                for (int c = 0; c < 4; c++) wb[c] = WB4[c * 128 + lane + 32 * j];
#pragma unroll
                for (int i = 0; i < 8; i++) {
                    float4 hv = __ldcg(&h1p[(w * 8 + i) * 128 + lane + 32 * j]);
#pragma unroll
                    for (int c = 0; c < 4; c++)
                        accB[i][c] += hv.x * wb[c].x + hv.y * wb[c].y
                                    + hv.z * wb[c].z + hv.w * wb[c].w;
                }
            }
            // reduce 32 k-partials per output through SMEM (stride-33: conflict-free)
#pragma unroll
            for (int i = 0; i < 8; i++)
#pragma unroll
                for (int c = 0; c < 4; c++)
                    Rs[(w * 32 + i * 4 + c) * 33 + lane] = accB[i][c];
            __syncthreads();
            float ssum = 0.f;
#pragma unroll
            for (int l = 0; l < 32; l++) ssum += Rs[(w * 32 + oi) * 33 + l];
            h1b = ssum;
        }

        // ---- wait for Hs stage; also closes the Rs read phase above ----
        asm volatile("cp.async.wait_group 0;\n" ::: "memory");
        __syncthreads();

        // ---- fused: h0-dot (Whh0) + h1A-dot (Wih1), both read Hs = h0[s-2] ----
        float acc0[8][4], accA[8][4];
#pragma unroll
        for (int i = 0; i < 8; i++)
#pragma unroll
            for (int c = 0; c < 4; c++) { acc0[i][c] = 0.f; accA[i][c] = 0.f; }
#pragma unroll
        for (int j = 0; j < 4; j++) {
            float4 w0[4], wa[4];
#pragma unroll
            for (int c = 0; c < 4; c++) {
                w0[c] = W04[c * 128 + lane + 32 * j];
                wa[c] = WA4[c * 128 + lane + 32 * j];
            }
#pragma unroll
            for (int i = 0; i < 8; i++) {
                float4 hv = Hs4[(w * 8 + i) * 128 + lane + 32 * j];
#pragma unroll
                for (int c = 0; c < 4; c++) {
                    acc0[i][c] += hv.x * w0[c].x + hv.y * w0[c].y
                                + hv.z * w0[c].z + hv.w * w0[c].w;
                    accA[i][c] += hv.x * wa[c].x + hv.y * wa[c].y
                                + hv.z * wa[c].z + hv.w * wa[c].w;
                }
            }
        }

        // ---- reduce + epilogue h0[s-1] ----
#pragma unroll
        for (int i = 0; i < 8; i++)
#pragma unroll
            for (int c = 0; c < 4; c++)
                Rs[(w * 32 + i * 4 + c) * 33 + lane] = acc0[i][c];
        __syncthreads();
        if (doH0) {
            float ssum = 0.f;
#pragma unroll
            for (int l = 0; l < 32; l++) ssum += Rs[(w * 32 + oi) * 33 + l];
            g_h0[(s - 1) & 1][b_r * H_N + c_r] = tanhf(ssum + xw);
        }
        __syncthreads();

        // ---- reduce + epilogue h1[s-2] ----
#pragma unroll
        for (int i = 0; i < 8; i++)
#pragma unroll
            for (int c = 0; c < 4; c++)
                Rs[(w * 32 + i * 4 + c) * 33 + lane] = accA[i][c];
        __syncthreads();
        if (doH1) {
            float ssum = 0.f;
#pragma unroll
            for (int l = 0; l < 32; l++) ssum += Rs[(w * 32 + oi) * 33 + l];
            float v = tanhf(ssum + h1b + b1s[c_loc]);
            g_h1[s & 1][b_r * H_N + c_r] = v;
            if (s == T_N + 1) __stcg(&out[b_r * H_N + c_r], v);
        }

        // ---- grid barrier (release/acquire; syncthreads provides intra-CTA hb) ----
        __syncthreads();
        if (tid == 0) {
            unsigned* bp = &g_bar[s];
            asm volatile("red.release.gpu.global.add.u32 [%0], 1;" :: "l"(bp) : "memory");
            unsigned v;
            asm volatile("ld.acquire.gpu.global.u32 %0, [%1];" : "=r"(v) : "l"(bp) : "memory");
            while (v < GRID_R) {
                __nanosleep(64);
                asm volatile("ld.acquire.gpu.global.u32 %0, [%1];" : "=r"(v) : "l"(bp) : "memory");
            }
        }
        __syncthreads();
    }
}

// ---------------- launch ----------------
extern "C" void kernel_launch(void* const* d_in, const int* in_sizes, int n_in,
                              void* d_out, int out_size) {
    const int*   input = (const int*)  d_in[0];
    const float* emb   = (const float*)d_in[1];
    const float* Wih0  = (const float*)d_in[2];
    const float* Whh0  = (const float*)d_in[3];
    const float* bih0  = (const float*)d_in[4];
    const float* bhh0  = (const float*)d_in[5];
    const float* Wih1  = (const float*)d_in[6];
    const float* Whh1  = (const float*)d_in[7];
    const float* bih1  = (const float*)d_in[8];
    const float* bhh1  = (const float*)d_in[9];
    float* out = (float*)d_out;

    cudaFuncSetAttribute(rnn_kernel, cudaFuncAttributeMaxDynamicSharedMemorySize, SMEM_BYTES);

    reset_kernel<<<(B_N * H_N + 255) / 256, 256>>>();
    embw_kernel<<<dim3(H_N / 128, V_N / 128), 256>>>(emb, Wih0, bih0, bhh0);
    rnn_kernel<<<GRID_R, NTHR, SMEM_BYTES>>>(input, Whh0, Wih1, Whh1, bih1, bhh1, out);
}

// round 4
// speedup vs baseline: 1.0448x; 1.0448x over previous
#include <cuda_runtime.h>
#include <cstdint>
#include <cstddef>

#define T_N   1024
#define B_N   64
#define V_N   32000
#define H_N   512

#define GC    32                 // col-members per group
#define GB    4                  // independent batch-groups
#define GRID_R (GC * GB)         // 128 CTAs
#define BPG   16                 // batches per group (64/4)
#define CPM   16                 // cols per member (512/32)
#define NTHR  256

// ---------------- persistent device scratch ----------------
__device__ float    g_embW0[(size_t)V_N * H_N];   // emb @ Wih0^T + bih0 + bhh0
__device__ float    g_h0[2][B_N * H_N];
__device__ float    g_h1[2][B_N * H_N];
__device__ unsigned g_flag[GRID_R * 8];           // per-CTA step flags (32B stride)

// ---------------- reset: deterministic per launch / graph replay ----------------
__global__ void reset_kernel() {
    int i = blockIdx.x * blockDim.x + threadIdx.x;
    if (i < B_N * H_N) {
        g_h0[0][i] = 0.f; g_h0[1][i] = 0.f;
        g_h1[0][i] = 0.f; g_h1[1][i] = 0.f;
    }
    if (i < GRID_R * 8) g_flag[i] = 0u;
}

// ---------------- embW0[v][h] = emb[v]·Wih0[h] + bih0[h] + bhh0[h] ----------------
__global__ __launch_bounds__(256) void embw_kernel(const float* __restrict__ A,
                                                   const float* __restrict__ W,
                                                   const float* __restrict__ bih,
                                                   const float* __restrict__ bhh) {
    __shared__ float As[8][132];
    __shared__ float Ws[8][132];
    const int tid   = threadIdx.x;
    const int hBase = blockIdx.x * 128;
    const int vBase = blockIdx.y * 128;
    const int lRow  = tid >> 1;
    const int lCol  = (tid & 1) * 4;
    const int tx    = tid & 15;
    const int ty    = tid >> 4;

    const float4* Ap = (const float4*)(A + (size_t)(vBase + lRow) * H_N + lCol);
    const float4* Wp = (const float4*)(W + (size_t)(hBase + lRow) * H_N + lCol);

    float acc[8][8];
#pragma unroll
    for (int i = 0; i < 8; i++)
#pragma unroll
        for (int j = 0; j < 8; j++) acc[i][j] = 0.f;

    float4 av = Ap[0];
    float4 wv = Wp[0];

    for (int k0 = 0; k0 < 512; k0 += 8) {
        __syncthreads();
        As[lCol + 0][lRow] = av.x; As[lCol + 1][lRow] = av.y;
        As[lCol + 2][lRow] = av.z; As[lCol + 3][lRow] = av.w;
        Ws[lCol + 0][lRow] = wv.x; Ws[lCol + 1][lRow] = wv.y;
        Ws[lCol + 2][lRow] = wv.z; Ws[lCol + 3][lRow] = wv.w;
        __syncthreads();
        if (k0 + 8 < 512) {
            av = Ap[(k0 + 8) >> 2];
            wv = Wp[(k0 + 8) >> 2];
        }
#pragma unroll
        for (int k = 0; k < 8; k++) {
            float a[8], w[8];
            *(float4*)&a[0] = *(const float4*)&As[k][ty * 8];
            *(float4*)&a[4] = *(const float4*)&As[k][ty * 8 + 4];
            *(float4*)&w[0] = *(const float4*)&Ws[k][tx * 8];
            *(float4*)&w[4] = *(const float4*)&Ws[k][tx * 8 + 4];
#pragma unroll
            for (int i = 0; i < 8; i++)
#pragma unroll
                for (int j = 0; j < 8; j++) acc[i][j] += a[i] * w[j];
        }
    }

#pragma unroll
    for (int i = 0; i < 8; i++) {
        const int v = vBase + ty * 8 + i;
        float* orow = &g_embW0[(size_t)v * H_N + hBase + tx * 8];
        float o[8];
#pragma unroll
        for (int j = 0; j < 8; j++) {
            int h = hBase + tx * 8 + j;
            o[j] = acc[i][j] + __ldg(&bih[h]) + __ldg(&bhh[h]);
        }
        *(float4*)&orow[0] = *(float4*)&o[0];
        *(float4*)&orow[4] = *(float4*)&o[4];
    }
}

// ---------------- persistent recurrence kernel (batch-grouped) ----------------
// SMEM floats: W0[8192] WA[8192] WB[8192] Hs0[8192] Hs1[8192] Rs[8448] b1[16]
#define OFF_W0 0
#define OFF_WA 8192
#define OFF_WB 16384
#define OFF_H0 24576
#define OFF_H1 32768
#define OFF_RS 40960
#define OFF_B1 (OFF_RS + 256 * 33)
#define SMEM_FLOATS (OFF_B1 + 16)
#define SMEM_BYTES  (SMEM_FLOATS * 4)

__global__ __launch_bounds__(NTHR, 1) void rnn_kernel(const int*   __restrict__ input,
                                                      const float* __restrict__ Whh0,
                                                      const float* __restrict__ Wih1,
                                                      const float* __restrict__ Whh1,
                                                      const float* __restrict__ bih1,
                                                      const float* __restrict__ bhh1,
                                                      float*       __restrict__ out) {
    extern __shared__ float smem[];
    float* W0s = smem + OFF_W0;
    float* WAs = smem + OFF_WA;
    float* WBs = smem + OFF_WB;
    float* Hs0 = smem + OFF_H0;
    float* Hs1 = smem + OFF_H1;
    float* Rs  = smem + OFF_RS;
    float* b1s = smem + OFF_B1;

    const int tid  = threadIdx.x;
    const int cid  = blockIdx.x;
    const int m    = cid & (GC - 1);   // member: owns cols [m*16, m*16+16)
    const int grp  = cid >> 5;         // group: owns batches [grp*16, grp*16+16)
    const int gb16 = grp * BPG;
    const int w    = tid >> 5;
    const int lane = tid & 31;
    const int o    = w >> 2;           // batch-oct within group (0..1)
    const int cc   = w & 3;            // col-quad within member (0..3)

    // ---- preload weight slices: rows [m*16, m*16+16) of each matrix ----
    {
        const float4* s0 = (const float4*)Whh0 + (size_t)m * 2048;
        const float4* s1 = (const float4*)Wih1 + (size_t)m * 2048;
        const float4* s2 = (const float4*)Whh1 + (size_t)m * 2048;
        float4* d0 = (float4*)W0s; float4* d1 = (float4*)WAs; float4* d2 = (float4*)WBs;
        for (int r = tid; r < 2048; r += NTHR) {
            d0[r] = __ldg(&s0[r]);
            d1[r] = __ldg(&s1[r]);
            d2[r] = __ldg(&s2[r]);
        }
        if (tid < CPM) b1s[tid] = __ldg(&bih1[m * CPM + tid]) + __ldg(&bhh1[m * CPM + tid]);
    }
    __syncthreads();

    // output decode (reduce-phase: thread tid owns output id tid)
    const int w_o    = tid >> 5;
    const int i_o    = (tid >> 2) & 7;
    const int c_o    = tid & 3;
    const int b_out  = gb16 + (w_o >> 2) * 8 + i_o;
    const int c_loc  = (w_o & 3) * 4 + c_o;
    const int c_glob = m * CPM + c_loc;

    const float4* W04 = (const float4*)W0s;
    const float4* WA4 = (const float4*)WAs;
    const float4* WB4 = (const float4*)WBs;
    const float4* H04 = (const float4*)Hs0;
    const float4* H14 = (const float4*)Hs1;
    const unsigned sd0 = (unsigned)__cvta_generic_to_shared(Hs0);
    const unsigned sd1 = (unsigned)__cvta_generic_to_shared(Hs1);

    for (int s = 1; s <= T_N + 1; s++) {
        const bool doH0 = (s <= T_N);
        const bool doH1 = (s >= 2);

        // ---- gather input-projection value early ----
        float xw = 0.f;
        if (doH0) {
            int tok = __ldg(&input[(s - 1) * B_N + b_out]);
            xw = __ldcg(&g_embW0[(size_t)tok * H_N + c_glob]);
        }

        // ---- stage group's h0[s-2], h1[s-3] rows: 4 k-chunk commit groups ----
        {
            const float* h0src = g_h0[s & 1];
            const float* h1src = g_h1[(s + 1) & 1];
#pragma unroll
            for (int j = 0; j < 4; j++) {
#pragma unroll
                for (int m2 = 0; m2 < 2; m2++) {
                    int l   = m2 * NTHR + tid;         // 0..511
                    int b_l = l >> 5;                   // 0..15
                    int c4  = l & 31;
                    size_t srcf4 = (size_t)(gb16 + b_l) * 128 + j * 32 + c4;
                    asm volatile("cp.async.cg.shared.global [%0], [%1], 16;\n"
                                 :: "r"(sd0 + (j * 512 + l) * 16), "l"(h0src + srcf4 * 4));
                    asm volatile("cp.async.cg.shared.global [%0], [%1], 16;\n"
                                 :: "r"(sd1 + (j * 512 + l) * 16), "l"(h1src + srcf4 * 4));
                }
                asm volatile("cp.async.commit_group;\n");
            }
        }

        float acc0[8][4], accA[8][4];
#pragma unroll
        for (int i = 0; i < 8; i++)
#pragma unroll
            for (int c = 0; c < 4; c++) { acc0[i][c] = 0.f; accA[i][c] = 0.f; }

        // ---- pass 1: h0 chunks -> acc0 (Whh0) and accA (Wih1) ----
#define PASS1_CHUNK(J, PEND)                                                     \
        {                                                                        \
            asm volatile("cp.async.wait_group " #PEND ";\n" ::: "memory");       \
            __syncthreads();                                                     \
            float4 w0q[4], waq[4];                                               \
            _Pragma("unroll")                                                    \
            for (int c = 0; c < 4; c++) {                                        \
                int row = cc * 4 + c;                                            \
                w0q[c] = W04[row * 128 + (J) * 32 + lane];                       \
                waq[c] = WA4[row * 128 + (J) * 32 + lane];                       \
            }                                                                    \
            _Pragma("unroll")                                                    \
            for (int i = 0; i < 8; i++) {                                        \
                float4 hv = H04[(J) * 512 + (o * 8 + i) * 32 + lane];            \
                _Pragma("unroll")                                                \
                for (int c = 0; c < 4; c++) {                                    \
                    acc0[i][c] += hv.x * w0q[c].x + hv.y * w0q[c].y              \
                                + hv.z * w0q[c].z + hv.w * w0q[c].w;             \
                    accA[i][c] += hv.x * waq[c].x + hv.y * waq[c].y              \
                                + hv.z * waq[c].z + hv.w * waq[c].w;             \
                }                                                                \
            }                                                                    \
        }
        PASS1_CHUNK(0, 3)
        PASS1_CHUNK(1, 2)
        PASS1_CHUNK(2, 1)
        PASS1_CHUNK(3, 0)
#undef PASS1_CHUNK

        // ---- pass 2: h1 chunks -> accA += (Whh1); all data already visible ----
#pragma unroll
        for (int j = 0; j < 4; j++) {
            float4 wbq[4];
#pragma unroll
            for (int c = 0; c < 4; c++)
                wbq[c] = WB4[(cc * 4 + c) * 128 + j * 32 + lane];
#pragma unroll
            for (int i = 0; i < 8; i++) {
                float4 hv = H14[j * 512 + (o * 8 + i) * 32 + lane];
#pragma unroll
                for (int c = 0; c < 4; c++)
                    accA[i][c] += hv.x * wbq[c].x + hv.y * wbq[c].y
                                + hv.z * wbq[c].z + hv.w * wbq[c].w;
            }
        }

        // ---- reduce phase 1: acc0 -> h0[s-1] ----
#pragma unroll
        for (int i = 0; i < 8; i++)
#pragma unroll
            for (int c = 0; c < 4; c++)
                Rs[(w * 32 + i * 4 + c) * 33 + lane] = acc0[i][c];
        __syncthreads();
        if (doH0) {
            float sum = 0.f;
#pragma unroll
            for (int l = 0; l < 32; l++) sum += Rs[tid * 33 + l];
            g_h0[(s - 1) & 1][b_out * H_N + c_glob] = tanhf(sum + xw);
        }
        __syncthreads();

        // ---- reduce phase 2: accA -> h1[s-2] ----
#pragma unroll
        for (int i = 0; i < 8; i++)
#pragma unroll
            for (int c = 0; c < 4; c++)
                Rs[(w * 32 + i * 4 + c) * 33 + lane] = accA[i][c];
        __syncthreads();
        if (doH1) {
            float sum = 0.f;
#pragma unroll
            for (int l = 0; l < 32; l++) sum += Rs[tid * 33 + l];
            float v = tanhf(sum + b1s[c_loc]);
            g_h1[s & 1][b_out * H_N + c_glob] = v;
            if (s == T_N + 1) __stcg(&out[b_out * H_N + c_glob], v);
        }

        // ---- group barrier: 32 members, flag-based ----
        __syncthreads();
        if (tid == 0) {
            __threadfence();
            asm volatile("st.relaxed.gpu.global.u32 [%0], %1;"
                         :: "l"(&g_flag[cid * 8]), "r"((unsigned)s) : "memory");
        }
        if (w == 0) {
            const unsigned* fp = &g_flag[(grp * GC + lane) * 8];
            unsigned v;
            do {
                asm volatile("ld.relaxed.gpu.global.u32 %0, [%1];"
                             : "=r"(v) : "l"(fp) : "memory");
            } while (__any_sync(0xffffffffu, v < (unsigned)s));
            __threadfence();
        }
        __syncthreads();
    }
}

// ---------------- launch ----------------
extern "C" void kernel_launch(void* const* d_in, const int* in_sizes, int n_in,
                              void* d_out, int out_size) {
    const int*   input = (const int*)  d_in[0];
    const float* emb   = (const float*)d_in[1];
    const float* Wih0  = (const float*)d_in[2];
    const float* Whh0  = (const float*)d_in[3];
    const float* bih0  = (const float*)d_in[4];
    const float* bhh0  = (const float*)d_in[5];
    const float* Wih1  = (const float*)d_in[6];
    const float* Whh1  = (const float*)d_in[7];
    const float* bih1  = (const float*)d_in[8];
    const float* bhh1  = (const float*)d_in[9];
    float* out = (float*)d_out;

    cudaFuncSetAttribute(rnn_kernel, cudaFuncAttributeMaxDynamicSharedMemorySize, SMEM_BYTES);

    reset_kernel<<<(B_N * H_N + 255) / 256, 256>>>();
    embw_kernel<<<dim3(H_N / 128, V_N / 128), 256>>>(emb, Wih0, bih0, bhh0);
    rnn_kernel<<<GRID_R, NTHR, SMEM_BYTES>>>(input, Whh0, Wih1, Whh1, bih1, bhh1, out);
}